// round 15
// baseline (speedup 1.0000x reference)
#include <cuda_runtime.h>

// GraphNet: 6x GraphConv (norm='both'), N=100000, E=1600000, final abs.
// Linear net => scalar-chain collapse (see R12/R14):
//   A1=S(ns.x), B1=S(ns);  Z2=S(nsnd.sa.A1);  Z_{k+1}=S(nsnd.(Z_k + c_k.B1));
//   out = | nd.(Z6 + s4.B1) + b5 |,  sigma from chained weight products.
//
// This round: ONE persistent kernel (296 blocks x 512 thr, launch_bounds(512,2)
// => guaranteed co-resident on 148 SMs) + software grid barriers, replacing 16
// kernel launches (~3us T_ovh each). Cross-phase reads of RED-written /
// rewritten data use __ldcg (L1 is not coherent across SMs within a launch).
// Edges packed as int4 pairs (2 edges / 16B load).

#define N_   100000
#define E_   1600000
#define EP_  (E_ / 2)
#define NBLK 296
#define NTHR 512
#define TOT  (NBLK * NTHR)

__device__ int4  g_edge[EP_];                       // {s0,d0,s1,d1}
__device__ float g_ns[N_], g_nd[N_], g_nsnd[N_];
__device__ __align__(8) float2 g_c1[N_];            // {ns*x, ns}
__device__ __align__(8) float2 g_P1[N_];            // {A1, B1}
__device__ float g_Z[2][N_];                        // ping-pong Z stages
__device__ float g_G[N_];                           // gather source per stage
__device__ float g_sig[8];                          // sa, s0, s1, s2, s3, s4
__device__ int   g_is64;
__device__ unsigned g_arrive;
__device__ volatile unsigned g_release;

// ---------------------------------------------------------------------------
__device__ __forceinline__ void red2(float2* a, float x, float y) {
    asm volatile("red.global.add.v2.f32 [%0], {%1,%2};"
                 :: "l"(a), "f"(x), "f"(y) : "memory");
}
__device__ __forceinline__ void red1(float* a, float x) {
    asm volatile("red.global.add.f32 [%0], %1;" :: "l"(a), "f"(x) : "memory");
}

// Software grid barrier #want (want = 1,2,...). Monotonic arrive counter, so
// no reset race; release flag observed via volatile (L1-bypassing) loads.
__device__ __forceinline__ void gbar(unsigned want) {
    __syncthreads();
    if (threadIdx.x == 0) {
        __threadfence();
        unsigned a = atomicAdd(&g_arrive, 1u);
        if (a == want * NBLK - 1u) {
            __threadfence();
            g_release = want;
        } else {
            while (g_release < want) __nanosleep(64);
        }
    }
    __syncthreads();
}

// ---------------------------------------------------------------------------
// Dense sigma algebra, run by all threads of block 0 (guards per section).
// sa=W0..W5, s0=b0W1..W5, s1=b1W2..W5, s2=b2W3W4W5, s3=b3W4W5, s4=b4W5.
__device__ void alg_block0(const float* __restrict__ W0, const float* __restrict__ b0,
                           const float* __restrict__ W1, const float* __restrict__ b1,
                           const float* __restrict__ W2, const float* __restrict__ b2,
                           const float* __restrict__ W3, const float* __restrict__ b3,
                           const float* __restrict__ W4, const float* __restrict__ b4,
                           const float* __restrict__ W5) {
    __shared__ float p1[64], q1[64];
    __shared__ float tP[128], tQ[128], tR[128];
    __shared__ float p2[64], q2[64], r2[64], s2v[64];
    __shared__ float p3[32], q3[32], r3[32], s3v[32], t3v[32];
    int t = threadIdx.x;

    if (t < 64) {
        float a = 0.f, b = 0.f;
        for (int c = 0; c < 32; c++) { a += W0[c] * W1[c * 64 + t]; b += b0[c] * W1[c * 64 + t]; }
        p1[t] = a; q1[t] = b;
    }
    __syncthreads();
    if (t < 128) {
        float a = 0.f, b = 0.f, r = 0.f;
        for (int c = 0; c < 64; c++) {
            float w = W2[c * 128 + t];
            a += p1[c] * w; b += q1[c] * w; r += b1[c] * w;
        }
        tP[t] = a; tQ[t] = b; tR[t] = r;
    }
    __syncthreads();
    if (t < 64) {
        float a = 0.f, b = 0.f, r = 0.f, s = 0.f;
        for (int k = 0; k < 128; k++) {
            float w = W3[k * 64 + t];
            a += tP[k] * w; b += tQ[k] * w; r += tR[k] * w; s += b2[k] * w;
        }
        p2[t] = a; q2[t] = b; r2[t] = r; s2v[t] = s;
    }
    __syncthreads();
    if (t < 32) {
        float a = 0.f, b = 0.f, r = 0.f, s = 0.f, tt = 0.f;
        for (int c = 0; c < 64; c++) {
            float w = W4[c * 32 + t];
            a += p2[c] * w; b += q2[c] * w; r += r2[c] * w; s += s2v[c] * w; tt += b3[c] * w;
        }
        p3[t] = a; q3[t] = b; r3[t] = r; s3v[t] = s; t3v[t] = tt;
    }
    __syncthreads();
    if (t == 0) {
        float sa = 0.f, s0 = 0.f, s1 = 0.f, ss2 = 0.f, ss3 = 0.f, s4 = 0.f;
        for (int c = 0; c < 32; c++) {
            float w = W5[c];
            sa += p3[c] * w; s0 += q3[c] * w; s1 += r3[c] * w;
            ss2 += s3v[c] * w; ss3 += t3v[c] * w; s4 += b4[c] * w;
        }
        g_sig[0] = sa; g_sig[1] = s0; g_sig[2] = s1;
        g_sig[3] = ss2; g_sig[4] = ss3; g_sig[5] = s4;
    }
}

// ---------------------------------------------------------------------------
__global__ void k_reset() {
    g_arrive = 0u;
    g_release = 0u;
    g_is64 = 1;
}

__global__ void __launch_bounds__(NTHR, 2)
k_main(const float* __restrict__ x,
       const int* __restrict__ s32, const int* __restrict__ d32,
       const float* __restrict__ W0, const float* __restrict__ b0,
       const float* __restrict__ W1, const float* __restrict__ b1,
       const float* __restrict__ W2, const float* __restrict__ b2,
       const float* __restrict__ W3, const float* __restrict__ b3,
       const float* __restrict__ W4, const float* __restrict__ b4,
       const float* __restrict__ W5, const float* __restrict__ b5,
       float* __restrict__ out) {
    const int tid = blockIdx.x * NTHR + threadIdx.x;
    unsigned ph = 0;

    // P0: zero degree/P1 buffers + index-dtype detect.
    // int64 LE (< 2^31): odd int32 words all zero; int32: some odd word != 0.
    for (int i = tid; i < N_; i += TOT) {
        g_ns[i] = 0.f; g_nd[i] = 0.f;
        g_P1[i] = make_float2(0.f, 0.f);
    }
    for (int i = tid; i < EP_; i += TOT)
        if (s32[2 * i + 1] != 0) g_is64 = 0;
    gbar(++ph);

    // P1: convert + pack edge pairs, degree REDs.
    {
        const int is64 = __ldcg(&g_is64);
        for (int t = tid; t < EP_; t += TOT) {
            int s0, d0, s1, d1;
            if (is64) {
                s0 = s32[4 * t]; s1 = s32[4 * t + 2];
                d0 = d32[4 * t]; d1 = d32[4 * t + 2];
            } else {
                int2 sv = *(const int2*)(s32 + 2 * t);
                int2 dv = *(const int2*)(d32 + 2 * t);
                s0 = sv.x; s1 = sv.y; d0 = dv.x; d1 = dv.y;
            }
            g_edge[t] = make_int4(s0, d0, s1, d1);
            red1(&g_ns[s0], 1.f); red1(&g_ns[s1], 1.f);
            red1(&g_nd[d0], 1.f); red1(&g_nd[d1], 1.f);
        }
    }
    gbar(++ph);

    // P2: norms (+fused {ns*x, ns}); block 0 also computes sigma.
    for (int i = tid; i < N_; i += TOT) {
        float ns = rsqrtf(fmaxf(__ldcg(&g_ns[i]), 1.f));
        float nd = rsqrtf(fmaxf(__ldcg(&g_nd[i]), 1.f));
        g_ns[i] = ns; g_nd[i] = nd; g_nsnd[i] = ns * nd;
        g_c1[i] = make_float2(ns * x[i], ns);
    }
    if (blockIdx.x == 0)
        alg_block0(W0, b0, W1, b1, W2, b2, W3, b3, W4, b4, W5);
    gbar(++ph);

    // P3: pass1 -> P1 = {A1, B1}
    for (int t = tid; t < EP_; t += TOT) {
        int4 e = g_edge[t];
        float2 p0 = g_c1[e.x];
        float2 p1 = g_c1[e.z];
        red2(&g_P1[e.y], p0.x, p0.y);
        red2(&g_P1[e.w], p1.x, p1.y);
    }
    gbar(++ph);

    // Stages 2..6: prep (G = nsnd*(Z_prev + c*B1), zero Z_cur) then scatter.
#pragma unroll
    for (int st = 2; st <= 6; ++st) {
        const int cur = st & 1;          // Z2->[0], Z3->[1], ..., Z6->[0]
        {
            const float sA = __ldcg(&g_sig[0]);
            const float c  = (st >= 3) ? __ldcg(&g_sig[st - 2]) : 0.f;
            for (int i = tid; i < N_; i += TOT) {
                float2 p = __ldcg(&g_P1[i]);
                float v = (st == 2) ? (sA * p.x)
                                    : (__ldcg(&g_Z[1 - cur][i]) + c * p.y);
                g_G[i] = g_nsnd[i] * v;      // nsnd: own-thread write in P2
                g_Z[cur][i] = 0.f;
            }
        }
        gbar(++ph);
        for (int t = tid; t < EP_; t += TOT) {
            int4 e = g_edge[t];
            red1(&g_Z[cur][e.y], __ldcg(&g_G[e.x]));
            red1(&g_Z[cur][e.w], __ldcg(&g_G[e.z]));
        }
        gbar(++ph);
    }

    // Final: out = | nd*(Z6 + s4*B1) + b5 |   (Z6 in g_Z[0])
    {
        const float s4 = __ldcg(&g_sig[5]);
        const float bb = b5[0];
        for (int i = tid; i < N_; i += TOT) {
            float y = __ldcg(&g_Z[0][i]) + s4 * __ldcg(&g_P1[i]).y;
            out[i] = fabsf(g_nd[i] * y + bb);
        }
    }
}

// ---------------------------------------------------------------------------
extern "C" void kernel_launch(void* const* d_in, const int* in_sizes, int n_in,
                              void* d_out, int out_size) {
    const float* x   = (const float*)d_in[0];
    const int*   src = (const int*)d_in[1];   // int32 view; dtype detected on-device
    const int*   dst = (const int*)d_in[2];
    const float *W0 = (const float*)d_in[3],  *b0 = (const float*)d_in[4];
    const float *W1 = (const float*)d_in[5],  *b1 = (const float*)d_in[6];
    const float *W2 = (const float*)d_in[7],  *b2 = (const float*)d_in[8];
    const float *W3 = (const float*)d_in[9],  *b3 = (const float*)d_in[10];
    const float *W4 = (const float*)d_in[11], *b4 = (const float*)d_in[12];
    const float *W5 = (const float*)d_in[13], *b5 = (const float*)d_in[14];
    float* out = (float*)d_out;

    k_reset<<<1, 1>>>();
    k_main<<<NBLK, NTHR>>>(x, src, dst, W0, b0, W1, b1, W2, b2,
                           W3, b3, W4, b4, W5, b5, out);
}